// round 5
// baseline (speedup 1.0000x reference)
#include <cuda_runtime.h>
#include <cuda_bf16.h>
#include <math.h>

#define B_TOK 32768
#define D_DIM 128
#define H_DIM 512
#define E_EXP 16
#define TM 64
#define NH 64
#define NCHUNK (H_DIM / NH)
#define THREADS 256

// SMEM byte offsets. X/B1 rows: 128+8=136 bf16 -> 272B. A2/B2 rows: 64+8=72 bf16 -> 144B.
#define OFF_TOKS 0
#define OFF_XH   256
#define OFF_XL   (OFF_XH + 17408)
#define OFF_B1H  (OFF_XL + 17408)
#define OFF_B1L  (OFF_B1H + 17408)
#define OFF_A2H  (OFF_B1L + 17408)
#define OFF_A2L  (OFF_A2H + 9216)
#define OFF_B2H  (OFF_A2L + 9216)
#define OFF_B2L  (OFF_B2H + 18432)
#define SMEM_TOTAL (OFF_B2L + 18432)

// ---------------- device scratch ----------------
__device__ int g_cnt[E_EXP];
__device__ int g_tok[E_EXP * B_TOK];

// ---------------- helpers ----------------
__device__ __forceinline__ void bsplit2(float v0, float v1, unsigned& hi, unsigned& lo) {
    __nv_bfloat162 h = __floats2bfloat162_rn(v0, v1);
    float r0 = v0 - __bfloat162float(h.x);
    float r1 = v1 - __bfloat162float(h.y);
    __nv_bfloat162 l = __floats2bfloat162_rn(r0, r1);
    hi = *(unsigned*)&h;
    lo = *(unsigned*)&l;
}
__device__ __forceinline__ void bsplit1(float v, unsigned short& h, unsigned short& l) {
    __nv_bfloat16 bh = __float2bfloat16(v);
    float r = v - __bfloat162float(bh);
    __nv_bfloat16 bl = __float2bfloat16(r);
    h = *(unsigned short*)&bh;
    l = *(unsigned short*)&bl;
}
__device__ __forceinline__ float gelu(float h) {
    return 0.5f * h * (1.0f + erff(h * 0.70710678118654752440f));
}
// D += A * B  (m16n8k16, bf16 in, fp32 acc) — base-PTX HMMA, valid on sm_103
__device__ __forceinline__ void mma16816(float* c, const unsigned* a, const unsigned* b) {
    asm volatile(
        "mma.sync.aligned.m16n8k16.row.col.f32.bf16.bf16.f32 "
        "{%0,%1,%2,%3}, {%4,%5,%6,%7}, {%8,%9}, {%0,%1,%2,%3};"
        : "+f"(c[0]), "+f"(c[1]), "+f"(c[2]), "+f"(c[3])
        : "r"(a[0]), "r"(a[1]), "r"(a[2]), "r"(a[3]), "r"(b[0]), "r"(b[1]));
}

// ---------------- kernel 0: reset counters ----------------
__global__ void zero_cnt_kernel() {
    if (threadIdx.x < E_EXP) g_cnt[threadIdx.x] = 0;
}

// ---------------- kernel 1: router (known-good) ----------------
__global__ __launch_bounds__(THREADS) void router_kernel(
    const float* __restrict__ x, const float* __restrict__ wg,
    const float* __restrict__ bg) {
    __shared__ float wgs[D_DIM * E_EXP];
    __shared__ float bgs[E_EXP];
    int tid = threadIdx.x;
    for (int i = tid; i < D_DIM * E_EXP; i += THREADS) wgs[i] = wg[i];
    if (tid < E_EXP) bgs[tid] = bg[tid];
    __syncthreads();

    int b = blockIdx.x * THREADS + tid;
    float acc[E_EXP];
#pragma unroll
    for (int e = 0; e < E_EXP; e++) acc[e] = bgs[e];
    const float4* xr = reinterpret_cast<const float4*>(x) + (size_t)b * (D_DIM / 4);
#pragma unroll 4
    for (int dq = 0; dq < D_DIM / 4; dq++) {
        float4 xv = xr[dq];
#pragma unroll
        for (int e = 0; e < E_EXP; e++) {
            acc[e] += xv.x * wgs[(dq * 4 + 0) * E_EXP + e];
            acc[e] += xv.y * wgs[(dq * 4 + 1) * E_EXP + e];
            acc[e] += xv.z * wgs[(dq * 4 + 2) * E_EXP + e];
            acc[e] += xv.w * wgs[(dq * 4 + 3) * E_EXP + e];
        }
    }
    int best = 0; float bv = acc[0];
#pragma unroll
    for (int e = 1; e < E_EXP; e++)
        if (acc[e] > bv) { bv = acc[e]; best = e; }

    unsigned lane = tid & 31;
    unsigned mask = __match_any_sync(0xffffffffu, best);
    int leader = __ffs(mask) - 1;
    int rank = __popc(mask & ((1u << lane) - 1u));
    int base = 0;
    if ((int)lane == leader) base = atomicAdd(&g_cnt[best], __popc(mask));
    base = __shfl_sync(0xffffffffu, base, leader);
    g_tok[best * B_TOK + base + rank] = b;
}

// ---------------- kernel 2: grouped MLP on HMMA (split-bf16, 3-MMA) ----------------
__global__ __launch_bounds__(THREADS, 1) void moe_mma_kernel(
    const float* __restrict__ x, const float* __restrict__ w1,
    const float* __restrict__ w2, float* __restrict__ out) {
    extern __shared__ char smem[];
    int e = blockIdx.x;
    int cnt = g_cnt[e];
    int start = blockIdx.y * TM;
    if (start >= cnt) return;
    int ntok = min(TM, cnt - start);
    int tid = threadIdx.x, wid = tid >> 5, lane = tid & 31;
    int g = lane >> 2, tg = lane & 3;
    int m0 = (wid & 3) * 16;
    int n0a = (wid >> 2) * 32;  // GEMM1 n-offset (64 cols over 2 warp groups)
    int n0b = (wid >> 2) * 64;  // GEMM2 n-offset (128 cols over 2 warp groups)

    int* toks = (int*)(smem + OFF_TOKS);
    if (tid < TM) toks[tid] = (tid < ntok) ? g_tok[e * B_TOK + start + tid] : -1;
    __syncthreads();

    // ---- gather X tile [64 tokens][128 d] fp32 -> split bf16 hi/lo, row stride 272B
    {
        int m = tid >> 2, q4 = tid & 3;
        int t = toks[m];
        const float4* xr = reinterpret_cast<const float4*>(x) +
                           (size_t)(t < 0 ? 0 : t) * 32 + q4 * 8;
#pragma unroll
        for (int i = 0; i < 8; i++) {
            float4 v = (t >= 0) ? xr[i] : make_float4(0.f, 0.f, 0.f, 0.f);
            int d = q4 * 32 + i * 4;
            unsigned hi, lo;
            bsplit2(v.x, v.y, hi, lo);
            *(unsigned*)(smem + OFF_XH + m * 272 + d * 2) = hi;
            *(unsigned*)(smem + OFF_XL + m * 272 + d * 2) = lo;
            bsplit2(v.z, v.w, hi, lo);
            *(unsigned*)(smem + OFF_XH + m * 272 + d * 2 + 4) = hi;
            *(unsigned*)(smem + OFF_XL + m * 272 + d * 2 + 4) = lo;
        }
    }

    const float* w1e = w1 + (size_t)e * D_DIM * H_DIM;
    const float* w2e = w2 + (size_t)e * H_DIM * D_DIM;

    float oacc[8][4];
#pragma unroll
    for (int i = 0; i < 8; i++)
#pragma unroll
        for (int j = 0; j < 4; j++) oacc[i][j] = 0.f;

    for (int c = 0; c < NCHUNK; c++) {
        int h0 = c * NH;
        __syncthreads();  // prev GEMM1 B1 reads + prev GEMM2 A2/B2 reads complete

        // ---- W1 chunk transpose: B1[h][d] hi/lo, pair-swizzle p ^= (h&7)<<3
#pragma unroll
        for (int it = 0; it < 8; it++) {
            int idx = tid + it * THREADS;       // 0..2047
            int d = idx >> 4, q = idx & 15;
            float4 v = reinterpret_cast<const float4*>(w1e + (size_t)d * H_DIM + h0)[q];
            float vv[4] = {v.x, v.y, v.z, v.w};
#pragma unroll
            for (int k = 0; k < 4; k++) {
                int h = q * 4 + k;
                unsigned short hh, ll;
                bsplit1(vv[k], hh, ll);
                unsigned p = (unsigned)(d >> 1) ^ ((unsigned)(h & 7) << 3);
                unsigned byte = (unsigned)h * 272 + p * 4 + (d & 1) * 2;
                *(unsigned short*)(smem + OFF_B1H + byte) = hh;
                *(unsigned short*)(smem + OFF_B1L + byte) = ll;
            }
        }
        __syncthreads();

        // ---- GEMM1: C1[16x32 per warp] = X @ W1c^T, 3-MMA split, K=128
        float acc1[4][4];
#pragma unroll
        for (int i = 0; i < 4; i++)
#pragma unroll
            for (int j = 0; j < 4; j++) acc1[i][j] = 0.f;

#pragma unroll
        for (int s = 0; s < 8; s++) {
            int kb = s * 16;
            unsigned ah[4], al[4];
            unsigned rb = (unsigned)(m0 + g) * 272 + kb * 2 + tg * 4;
            ah[0] = *(const unsigned*)(smem + OFF_XH + rb);
            ah[1] = *(const unsigned*)(smem + OFF_XH + rb + 8 * 272);
            ah[2] = *(const unsigned*)(smem + OFF_XH + rb + 16);
            ah[3] = *(const unsigned*)(smem + OFF_XH + rb + 8 * 272 + 16);
            al[0] = *(const unsigned*)(smem + OFF_XL + rb);
            al[1] = *(const unsigned*)(smem + OFF_XL + rb + 8 * 272);
            al[2] = *(const unsigned*)(smem + OFF_XL + rb + 16);
            al[3] = *(const unsigned*)(smem + OFF_XL + rb + 8 * 272 + 16);
#pragma unroll
            for (int nf = 0; nf < 4; nf++) {
                int h = n0a + nf * 8 + g;
                unsigned p0 = ((unsigned)(kb >> 1) + tg) ^ ((unsigned)g << 3);
                unsigned bb = (unsigned)h * 272 + p0 * 4;
                unsigned bh[2], bl[2];
                bh[0] = *(const unsigned*)(smem + OFF_B1H + bb);
                bh[1] = *(const unsigned*)(smem + OFF_B1H + bb + 16);
                bl[0] = *(const unsigned*)(smem + OFF_B1L + bb);
                bl[1] = *(const unsigned*)(smem + OFF_B1L + bb + 16);
                mma16816(acc1[nf], ah, bh);
                mma16816(acc1[nf], ah, bl);
                mma16816(acc1[nf], al, bh);
            }
        }

        // ---- GELU + split -> A2[m][h] hi/lo (row stride 144B, no swizzle needed)
#pragma unroll
        for (int nf = 0; nf < 4; nf++) {
            int col = n0a + nf * 8 + tg * 2;
            unsigned hi, lo;
            bsplit2(gelu(acc1[nf][0]), gelu(acc1[nf][1]), hi, lo);
            *(unsigned*)(smem + OFF_A2H + (m0 + g) * 144 + col * 2) = hi;
            *(unsigned*)(smem + OFF_A2L + (m0 + g) * 144 + col * 2) = lo;
            bsplit2(gelu(acc1[nf][2]), gelu(acc1[nf][3]), hi, lo);
            *(unsigned*)(smem + OFF_A2H + (m0 + g + 8) * 144 + col * 2) = hi;
            *(unsigned*)(smem + OFF_A2L + (m0 + g + 8) * 144 + col * 2) = lo;
        }

        // ---- W2 chunk transpose: B2[d][h] hi/lo, pair-swizzle p ^= (d&7)<<2
#pragma unroll
        for (int it = 0; it < 8; it++) {
            int idx = tid + it * THREADS;       // 0..2047
            int j = idx >> 5, dq = idx & 31;
            float4 v = reinterpret_cast<const float4*>(w2e + (size_t)(h0 + j) * D_DIM)[dq];
            float vv[4] = {v.x, v.y, v.z, v.w};
#pragma unroll
            for (int k = 0; k < 4; k++) {
                int d = dq * 4 + k;
                unsigned short hh, ll;
                bsplit1(vv[k], hh, ll);
                unsigned p = (unsigned)(j >> 1) ^ ((unsigned)(d & 7) << 2);
                unsigned byte = (unsigned)d * 144 + p * 4 + (j & 1) * 2;
                *(unsigned short*)(smem + OFF_B2H + byte) = hh;
                *(unsigned short*)(smem + OFF_B2L + byte) = ll;
            }
        }
        __syncthreads();

        // ---- GEMM2: out[16x64 per warp] += gelu(H) @ W2c^T, K=64
#pragma unroll
        for (int s = 0; s < 4; s++) {
            int kb = s * 16;
            unsigned ah[4], al[4];
            unsigned rb = (unsigned)(m0 + g) * 144 + kb * 2 + tg * 4;
            ah[0] = *(const unsigned*)(smem + OFF_A2H + rb);
            ah[1] = *(const unsigned*)(smem + OFF_A2H + rb + 8 * 144);
            ah[2] = *(const unsigned*)(smem + OFF_A2H + rb + 16);
            ah[3] = *(const unsigned*)(smem + OFF_A2H + rb + 8 * 144 + 16);
            al[0] = *(const unsigned*)(smem + OFF_A2L + rb);
            al[1] = *(const unsigned*)(smem + OFF_A2L + rb + 8 * 144);
            al[2] = *(const unsigned*)(smem + OFF_A2L + rb + 16);
            al[3] = *(const unsigned*)(smem + OFF_A2L + rb + 8 * 144 + 16);
#pragma unroll
            for (int nf = 0; nf < 8; nf++) {
                int d = n0b + nf * 8 + g;
                unsigned base = (unsigned)(kb >> 1) + tg;
                unsigned p0 = base ^ ((unsigned)g << 2);
                unsigned p1 = (base + 4) ^ ((unsigned)g << 2);
                unsigned bh[2], bl[2];
                bh[0] = *(const unsigned*)(smem + OFF_B2H + (unsigned)d * 144 + p0 * 4);
                bh[1] = *(const unsigned*)(smem + OFF_B2H + (unsigned)d * 144 + p1 * 4);
                bl[0] = *(const unsigned*)(smem + OFF_B2L + (unsigned)d * 144 + p0 * 4);
                bl[1] = *(const unsigned*)(smem + OFF_B2L + (unsigned)d * 144 + p1 * 4);
                mma16816(oacc[nf], ah, bh);
                mma16816(oacc[nf], ah, bl);
                mma16816(oacc[nf], al, bh);
            }
        }
    }

    // ---- scatter output rows
#pragma unroll
    for (int nf = 0; nf < 8; nf++) {
        int col = n0b + nf * 8 + tg * 2;
        int m1 = m0 + g, m2 = m0 + g + 8;
        if (m1 < ntok) {
            int t = toks[m1];
            *reinterpret_cast<float2*>(out + (size_t)t * D_DIM + col) =
                make_float2(oacc[nf][0], oacc[nf][1]);
        }
        if (m2 < ntok) {
            int t = toks[m2];
            *reinterpret_cast<float2*>(out + (size_t)t * D_DIM + col) =
                make_float2(oacc[nf][2], oacc[nf][3]);
        }
    }
}

// ---------------- launcher ----------------
extern "C" void kernel_launch(void* const* d_in, const int* in_sizes, int n_in,
                              void* d_out, int out_size) {
    const float* x  = (const float*)d_in[0];
    const float* w1 = (const float*)d_in[1];
    const float* w2 = (const float*)d_in[2];
    const float* wg = (const float*)d_in[3];
    const float* bg = (const float*)d_in[4];
    float* out = (float*)d_out;

    cudaFuncSetAttribute(moe_mma_kernel, cudaFuncAttributeMaxDynamicSharedMemorySize,
                         SMEM_TOTAL);

    zero_cnt_kernel<<<1, E_EXP>>>();
    router_kernel<<<B_TOK / THREADS, THREADS>>>(x, wg, bg);
    dim3 grid(E_EXP, B_TOK / TM);  // capacity grid: no token dropped
    moe_mma_kernel<<<grid, THREADS, SMEM_TOTAL>>>(x, w1, w2, out);
}

// round 6
// speedup vs baseline: 2.7716x; 2.7716x over previous
#include <cuda_runtime.h>
#include <cuda_bf16.h>
#include <math.h>

#define B_TOK 32768
#define D_DIM 128
#define H_DIM 512
#define E_EXP 16
#define TM 64
#define NH 64
#define NCHUNK (H_DIM / NH)
#define THREADS 256

// weight image sizes (bytes): B1 rows 64x272 (64 data words + 4 pad), B2 rows 128x144
#define W1BUF 17408
#define W2BUF 18432
#define CHUNK_BYTES (2 * W1BUF + 2 * W2BUF)  // 71680

// SMEM layout (all offsets 16B-aligned)
#define OFF_TOKS 0
#define OFF_XH   256
#define OFF_XL   (OFF_XH + 17408)
#define OFF_A2H  (OFF_XL + 17408)
#define OFF_A2L  (OFF_A2H + 9216)
#define OFF_BUF0 (OFF_A2L + 9216)
#define SMEM_TOTAL (OFF_BUF0 + 2 * CHUNK_BYTES)  // 196864

// ---------------- device scratch ----------------
__device__ int g_cnt[E_EXP];
__device__ int g_tok[E_EXP * B_TOK];
__device__ unsigned char g_wt[E_EXP][NCHUNK][CHUNK_BYTES];  // pre-swizzled weights

// ---------------- helpers ----------------
__device__ __forceinline__ void bsplit2(float v0, float v1, unsigned& hi, unsigned& lo) {
    __nv_bfloat162 h = __floats2bfloat162_rn(v0, v1);
    float r0 = v0 - __bfloat162float(h.x);
    float r1 = v1 - __bfloat162float(h.y);
    __nv_bfloat162 l = __floats2bfloat162_rn(r0, r1);
    hi = *(unsigned*)&h;
    lo = *(unsigned*)&l;
}
__device__ __forceinline__ float gelu(float h) {
    return 0.5f * h * (1.0f + erff(h * 0.70710678118654752440f));
}
__device__ __forceinline__ unsigned smem_u32(const void* p) {
    unsigned a;
    asm("{ .reg .u64 t; cvta.to.shared.u64 t, %1; cvt.u32.u64 %0, t; }"
        : "=r"(a) : "l"(p));
    return a;
}
__device__ __forceinline__ void cp_async16(unsigned dst, const void* src) {
    asm volatile("cp.async.cg.shared.global [%0], [%1], 16;"
                 :: "r"(dst), "l"(src) : "memory");
}
#define CP_COMMIT() asm volatile("cp.async.commit_group;" ::: "memory")
#define CP_WAIT(n)  asm volatile("cp.async.wait_group %0;" :: "n"(n) : "memory")

// D += A * B  (m16n8k16, bf16 in, fp32 acc) — base-PTX HMMA, valid on sm_103
__device__ __forceinline__ void mma16816(float* c, const unsigned* a, const unsigned* b) {
    asm volatile(
        "mma.sync.aligned.m16n8k16.row.col.f32.bf16.bf16.f32 "
        "{%0,%1,%2,%3}, {%4,%5,%6,%7}, {%8,%9}, {%0,%1,%2,%3};"
        : "+f"(c[0]), "+f"(c[1]), "+f"(c[2]), "+f"(c[3])
        : "r"(a[0]), "r"(a[1]), "r"(a[2]), "r"(a[3]), "r"(b[0]), "r"(b[1]));
}

// ---------------- kernel 0: reset counters ----------------
__global__ void zero_cnt_kernel() {
    if (threadIdx.x < E_EXP) g_cnt[threadIdx.x] = 0;
}

// ---------------- kernel P: pre-swizzle weights into the SMEM image ----------------
// B1 word (h, p): d-pair dp = p ^ ((h&7)<<3); low16 = d even, high16 = d odd.
// B2 word (d, p): j-pair jp = p ^ ((d&7)<<2); low16 = j even, high16 = j odd.
__global__ __launch_bounds__(THREADS) void prep_kernel(
    const float* __restrict__ w1, const float* __restrict__ w2) {
    int e = blockIdx.x, c = blockIdx.y;
    int h0 = c * NH;
    const float* w1e = w1 + (size_t)e * D_DIM * H_DIM;
    const float* w2e = w2 + (size_t)e * H_DIM * D_DIM;
    unsigned char* dst = g_wt[e][c];

    for (int i = threadIdx.x; i < W1BUF / 4; i += THREADS) {  // 4352 words
        int h = i / 68, w = i % 68;
        if (w < 64) {
            int dp = w ^ ((h & 7) << 3);
            float v0 = w1e[(size_t)(2 * dp) * H_DIM + h0 + h];
            float v1 = w1e[(size_t)(2 * dp + 1) * H_DIM + h0 + h];
            unsigned hi, lo;
            bsplit2(v0, v1, hi, lo);
            *(unsigned*)(dst + i * 4) = hi;
            *(unsigned*)(dst + W1BUF + i * 4) = lo;
        }
    }
    for (int i = threadIdx.x; i < W2BUF / 4; i += THREADS) {  // 4608 words
        int d = i / 36, w = i % 36;
        if (w < 32) {
            int jp = w ^ ((d & 7) << 2);
            float v0 = w2e[(size_t)(h0 + 2 * jp) * D_DIM + d];
            float v1 = w2e[(size_t)(h0 + 2 * jp + 1) * D_DIM + d];
            unsigned hi, lo;
            bsplit2(v0, v1, hi, lo);
            *(unsigned*)(dst + 2 * W1BUF + i * 4) = hi;
            *(unsigned*)(dst + 2 * W1BUF + W2BUF + i * 4) = lo;
        }
    }
}

// ---------------- kernel 1: router (known-good) ----------------
__global__ __launch_bounds__(THREADS) void router_kernel(
    const float* __restrict__ x, const float* __restrict__ wg,
    const float* __restrict__ bg) {
    __shared__ float wgs[D_DIM * E_EXP];
    __shared__ float bgs[E_EXP];
    int tid = threadIdx.x;
    for (int i = tid; i < D_DIM * E_EXP; i += THREADS) wgs[i] = wg[i];
    if (tid < E_EXP) bgs[tid] = bg[tid];
    __syncthreads();

    int b = blockIdx.x * THREADS + tid;
    float acc[E_EXP];
#pragma unroll
    for (int e = 0; e < E_EXP; e++) acc[e] = bgs[e];
    const float4* xr = reinterpret_cast<const float4*>(x) + (size_t)b * (D_DIM / 4);
#pragma unroll 4
    for (int dq = 0; dq < D_DIM / 4; dq++) {
        float4 xv = xr[dq];
#pragma unroll
        for (int e = 0; e < E_EXP; e++) {
            acc[e] += xv.x * wgs[(dq * 4 + 0) * E_EXP + e];
            acc[e] += xv.y * wgs[(dq * 4 + 1) * E_EXP + e];
            acc[e] += xv.z * wgs[(dq * 4 + 2) * E_EXP + e];
            acc[e] += xv.w * wgs[(dq * 4 + 3) * E_EXP + e];
        }
    }
    int best = 0; float bv = acc[0];
#pragma unroll
    for (int e = 1; e < E_EXP; e++)
        if (acc[e] > bv) { bv = acc[e]; best = e; }

    unsigned lane = tid & 31;
    unsigned mask = __match_any_sync(0xffffffffu, best);
    int leader = __ffs(mask) - 1;
    int rank = __popc(mask & ((1u << lane) - 1u));
    int base = 0;
    if ((int)lane == leader) base = atomicAdd(&g_cnt[best], __popc(mask));
    base = __shfl_sync(0xffffffffu, base, leader);
    g_tok[best * B_TOK + base + rank] = b;
}

// ---------------- kernel 2: grouped MLP on HMMA, pre-swizzled weights ----------------
__global__ __launch_bounds__(THREADS, 1) void moe_mma_kernel(
    const float* __restrict__ x, float* __restrict__ out) {
    extern __shared__ char smem[];
    int e = blockIdx.x;
    int cnt = g_cnt[e];
    int start = blockIdx.y * TM;
    if (start >= cnt) return;
    int ntok = min(TM, cnt - start);
    int tid = threadIdx.x, wid = tid >> 5, lane = tid & 31;
    int g = lane >> 2, tg = lane & 3;
    int m0 = (wid & 3) * 16;
    int n0a = (wid >> 2) * 32;  // GEMM1 n-offset
    int n0b = (wid >> 2) * 64;  // GEMM2 n-offset
    unsigned sb = smem_u32(smem);

    int* toks = (int*)(smem + OFF_TOKS);
    if (tid < TM) toks[tid] = (tid < ntok) ? g_tok[e * B_TOK + start + tid] : -1;
    __syncthreads();

    // ---- gather X tile [64][128] fp32 -> split bf16 hi/lo (row stride 272B)
    {
        int m = tid >> 2, q4 = tid & 3;
        int t = toks[m];
        const float4* xr = reinterpret_cast<const float4*>(x) +
                           (size_t)(t < 0 ? 0 : t) * 32 + q4 * 8;
#pragma unroll
        for (int i = 0; i < 8; i++) {
            float4 v = (t >= 0) ? xr[i] : make_float4(0.f, 0.f, 0.f, 0.f);
            int d = q4 * 32 + i * 4;
            unsigned hi, lo;
            bsplit2(v.x, v.y, hi, lo);
            *(unsigned*)(smem + OFF_XH + m * 272 + d * 2) = hi;
            *(unsigned*)(smem + OFF_XL + m * 272 + d * 2) = lo;
            bsplit2(v.z, v.w, hi, lo);
            *(unsigned*)(smem + OFF_XH + m * 272 + d * 2 + 4) = hi;
            *(unsigned*)(smem + OFF_XL + m * 272 + d * 2 + 4) = lo;
        }
    }

    // ---- prologue: prefetch chunk 0 weights into buf0
    {
        const unsigned char* src = g_wt[e][0];
        unsigned dst = sb + OFF_BUF0;
        for (int i = tid; i < CHUNK_BYTES / 16; i += THREADS)
            cp_async16(dst + i * 16, src + i * 16);
        CP_COMMIT();
    }

    float oacc[8][4];
#pragma unroll
    for (int i = 0; i < 8; i++)
#pragma unroll
        for (int j = 0; j < 4; j++) oacc[i][j] = 0.f;

    for (int c = 0; c < NCHUNK; c++) {
        // prefetch next chunk into the other buffer (its readers finished last iter)
        if (c + 1 < NCHUNK) {
            const unsigned char* src = g_wt[e][c + 1];
            unsigned dst = sb + OFF_BUF0 + ((c + 1) & 1) * CHUNK_BYTES;
            for (int i = tid; i < CHUNK_BYTES / 16; i += THREADS)
                cp_async16(dst + i * 16, src + i * 16);
            CP_COMMIT();
            CP_WAIT(1);   // current chunk's copy complete
        } else {
            CP_WAIT(0);
        }
        __syncthreads();  // buf[c&1] visible; X visible (c==0); prev A2 readers done

        const char* bufb = smem + OFF_BUF0 + (c & 1) * CHUNK_BYTES;
        const char* B1H = bufb;
        const char* B1L = bufb + W1BUF;
        const char* B2H = bufb + 2 * W1BUF;
        const char* B2L = bufb + 2 * W1BUF + W2BUF;

        // ---- GEMM1: C1[16x32 per warp] = X @ W1c^T, 3-MMA split, K=128
        float acc1[4][4];
#pragma unroll
        for (int i = 0; i < 4; i++)
#pragma unroll
            for (int j = 0; j < 4; j++) acc1[i][j] = 0.f;

#pragma unroll
        for (int s = 0; s < 8; s++) {
            int kb = s * 16;
            unsigned ah[4], al[4];
            unsigned rb = (unsigned)(m0 + g) * 272 + kb * 2 + tg * 4;
            ah[0] = *(const unsigned*)(smem + OFF_XH + rb);
            ah[1] = *(const unsigned*)(smem + OFF_XH + rb + 8 * 272);
            ah[2] = *(const unsigned*)(smem + OFF_XH + rb + 16);
            ah[3] = *(const unsigned*)(smem + OFF_XH + rb + 8 * 272 + 16);
            al[0] = *(const unsigned*)(smem + OFF_XL + rb);
            al[1] = *(const unsigned*)(smem + OFF_XL + rb + 8 * 272);
            al[2] = *(const unsigned*)(smem + OFF_XL + rb + 16);
            al[3] = *(const unsigned*)(smem + OFF_XL + rb + 8 * 272 + 16);
#pragma unroll
            for (int nf = 0; nf < 4; nf++) {
                int h = n0a + nf * 8 + g;
                unsigned p0 = ((unsigned)(kb >> 1) + tg) ^ ((unsigned)g << 3);
                unsigned bb = (unsigned)h * 272 + p0 * 4;
                unsigned bh[2], bl[2];
                bh[0] = *(const unsigned*)(B1H + bb);
                bh[1] = *(const unsigned*)(B1H + bb + 16);
                bl[0] = *(const unsigned*)(B1L + bb);
                bl[1] = *(const unsigned*)(B1L + bb + 16);
                mma16816(acc1[nf], ah, bh);
                mma16816(acc1[nf], ah, bl);
                mma16816(acc1[nf], al, bh);
            }
        }

        // ---- GELU + split -> A2[m][h] hi/lo (row stride 144B)
#pragma unroll
        for (int nf = 0; nf < 4; nf++) {
            int col = n0a + nf * 8 + tg * 2;
            unsigned hi, lo;
            bsplit2(gelu(acc1[nf][0]), gelu(acc1[nf][1]), hi, lo);
            *(unsigned*)(smem + OFF_A2H + (m0 + g) * 144 + col * 2) = hi;
            *(unsigned*)(smem + OFF_A2L + (m0 + g) * 144 + col * 2) = lo;
            bsplit2(gelu(acc1[nf][2]), gelu(acc1[nf][3]), hi, lo);
            *(unsigned*)(smem + OFF_A2H + (m0 + g + 8) * 144 + col * 2) = hi;
            *(unsigned*)(smem + OFF_A2L + (m0 + g + 8) * 144 + col * 2) = lo;
        }
        __syncthreads();  // A2 visible to GEMM2

        // ---- GEMM2: out[16x64 per warp] += gelu(H) @ W2c^T, K=64
#pragma unroll
        for (int s = 0; s < 4; s++) {
            int kb = s * 16;
            unsigned ah[4], al[4];
            unsigned rb = (unsigned)(m0 + g) * 144 + kb * 2 + tg * 4;
            ah[0] = *(const unsigned*)(smem + OFF_A2H + rb);
            ah[1] = *(const unsigned*)(smem + OFF_A2H + rb + 8 * 144);
            ah[2] = *(const unsigned*)(smem + OFF_A2H + rb + 16);
            ah[3] = *(const unsigned*)(smem + OFF_A2H + rb + 8 * 144 + 16);
            al[0] = *(const unsigned*)(smem + OFF_A2L + rb);
            al[1] = *(const unsigned*)(smem + OFF_A2L + rb + 8 * 144);
            al[2] = *(const unsigned*)(smem + OFF_A2L + rb + 16);
            al[3] = *(const unsigned*)(smem + OFF_A2L + rb + 8 * 144 + 16);
#pragma unroll
            for (int nf = 0; nf < 8; nf++) {
                int d = n0b + nf * 8 + g;
                unsigned base = (unsigned)(kb >> 1) + tg;
                unsigned p0 = base ^ ((unsigned)g << 2);
                unsigned p1 = (base + 4) ^ ((unsigned)g << 2);
                unsigned bh[2], bl[2];
                bh[0] = *(const unsigned*)(B2H + (unsigned)d * 144 + p0 * 4);
                bh[1] = *(const unsigned*)(B2H + (unsigned)d * 144 + p1 * 4);
                bl[0] = *(const unsigned*)(B2L + (unsigned)d * 144 + p0 * 4);
                bl[1] = *(const unsigned*)(B2L + (unsigned)d * 144 + p1 * 4);
                mma16816(oacc[nf], ah, bh);
                mma16816(oacc[nf], ah, bl);
                mma16816(oacc[nf], al, bh);
            }
        }
        __syncthreads();  // buf + A2 reads done before next-iter overwrite
    }

    // ---- scatter output rows
#pragma unroll
    for (int nf = 0; nf < 8; nf++) {
        int col = n0b + nf * 8 + tg * 2;
        int m1 = m0 + g, m2 = m0 + g + 8;
        if (m1 < ntok) {
            int t = toks[m1];
            *reinterpret_cast<float2*>(out + (size_t)t * D_DIM + col) =
                make_float2(oacc[nf][0], oacc[nf][1]);
        }
        if (m2 < ntok) {
            int t = toks[m2];
            *reinterpret_cast<float2*>(out + (size_t)t * D_DIM + col) =
                make_float2(oacc[nf][2], oacc[nf][3]);
        }
    }
}

// ---------------- launcher ----------------
extern "C" void kernel_launch(void* const* d_in, const int* in_sizes, int n_in,
                              void* d_out, int out_size) {
    const float* x  = (const float*)d_in[0];
    const float* w1 = (const float*)d_in[1];
    const float* w2 = (const float*)d_in[2];
    const float* wg = (const float*)d_in[3];
    const float* bg = (const float*)d_in[4];
    float* out = (float*)d_out;

    cudaFuncSetAttribute(moe_mma_kernel, cudaFuncAttributeMaxDynamicSharedMemorySize,
                         SMEM_TOTAL);

    zero_cnt_kernel<<<1, E_EXP>>>();
    router_kernel<<<B_TOK / THREADS, THREADS>>>(x, wg, bg);
    dim3 pgrid(E_EXP, NCHUNK);
    prep_kernel<<<pgrid, THREADS>>>(w1, w2);
    dim3 grid(E_EXP, B_TOK / TM);  // capacity grid: no token dropped
    moe_mma_kernel<<<grid, THREADS, SMEM_TOTAL>>>(x, out);
}

// round 9
// speedup vs baseline: 3.6577x; 1.3197x over previous
#include <cuda_runtime.h>
#include <cuda_bf16.h>
#include <math.h>

#define B_TOK 32768
#define D_DIM 128
#define H_DIM 512
#define E_EXP 16
#define TM 64
#define NH 32
#define NCHUNK (H_DIM / NH)   // 16
#define THREADS 256

// weight image sizes (bytes)
#define W1HALF 8704           // 32 h-rows x 272B (64 d-pair words + 4 pad words)
#define W1CH   (2 * W1HALF)   // 17408 (hi + lo)
#define W2HALF 10240          // 128 d-rows x 80B (16 j-pair words + 4 pad words)
#define W2CH   (2 * W2HALF)   // 20480
#define CHUNK_BYTES (W1CH + W2CH)  // 37888

// SMEM layout (bytes)
#define OFF_TOKS 0
#define OFF_XH   256
#define OFF_XL   (OFF_XH + 17408)
#define OFF_A2H  (OFF_XL + 17408)
#define OFF_A2L  (OFF_A2H + 5120)
#define OFF_W1   (OFF_A2L + 5120)            // double buffer: + buf*W1CH, each [H|L]
#define OFF_W2   (OFF_W1 + 2 * W1CH)         // single buffer: [H|L]
#define SMEM_TOTAL (OFF_W2 + W2CH)           // 100608 -> 2 CTAs/SM

// ---------------- device scratch ----------------
__device__ int g_cnt[E_EXP];
__device__ int g_tok[E_EXP * B_TOK];
__device__ unsigned char g_wt[E_EXP][NCHUNK][CHUNK_BYTES];  // pre-split weight images

// ---------------- helpers ----------------
__device__ __forceinline__ void bsplit2(float v0, float v1, unsigned& hi, unsigned& lo) {
    __nv_bfloat162 h = __floats2bfloat162_rn(v0, v1);
    float r0 = v0 - __bfloat162float(h.x);
    float r1 = v1 - __bfloat162float(h.y);
    __nv_bfloat162 l = __floats2bfloat162_rn(r0, r1);
    hi = *(unsigned*)&h;
    lo = *(unsigned*)&l;
}
__device__ __forceinline__ float gelu(float h) {
    return 0.5f * h * (1.0f + erff(h * 0.70710678118654752440f));
}
__device__ __forceinline__ unsigned smem_u32(const void* p) {
    unsigned a;
    asm("{ .reg .u64 t; cvta.to.shared.u64 t, %1; cvt.u32.u64 %0, t; }"
        : "=r"(a) : "l"(p));
    return a;
}
__device__ __forceinline__ void cp_async16(unsigned dst, const void* src) {
    asm volatile("cp.async.cg.shared.global [%0], [%1], 16;"
                 :: "r"(dst), "l"(src) : "memory");
}
#define CP_COMMIT() asm volatile("cp.async.commit_group;" ::: "memory")
#define CP_WAIT(n)  asm volatile("cp.async.wait_group %0;" :: "n"(n) : "memory")

// D += A * B  (m16n8k16, bf16 in, fp32 acc) — base-PTX HMMA, valid on sm_103
__device__ __forceinline__ void mma16816(float* c, const unsigned* a, const unsigned* b) {
    asm volatile(
        "mma.sync.aligned.m16n8k16.row.col.f32.bf16.bf16.f32 "
        "{%0,%1,%2,%3}, {%4,%5,%6,%7}, {%8,%9}, {%0,%1,%2,%3};"
        : "+f"(c[0]), "+f"(c[1]), "+f"(c[2]), "+f"(c[3])
        : "r"(a[0]), "r"(a[1]), "r"(a[2]), "r"(a[3]), "r"(b[0]), "r"(b[1]));
}

// ---------------- kernel 0: reset counters ----------------
__global__ void zero_cnt_kernel() {
    if (threadIdx.x < E_EXP) g_cnt[threadIdx.x] = 0;
}

// ---------------- kernel P: pre-split weights into linear SMEM images ----------------
// B1 word (h, w<64): d-pair dp = w; low16 = d even, high16 = d odd.
// B2 word (d, w<16): j-pair jp = w; low16 = j even, high16 = j odd.
__global__ __launch_bounds__(THREADS) void prep_kernel(
    const float* __restrict__ w1, const float* __restrict__ w2) {
    int e = blockIdx.x, c = blockIdx.y;
    int h0 = c * NH;
    const float* w1e = w1 + (size_t)e * D_DIM * H_DIM;
    const float* w2e = w2 + (size_t)e * H_DIM * D_DIM;
    unsigned char* dst = g_wt[e][c];

    for (int i = threadIdx.x; i < W1HALF / 4; i += THREADS) {  // 2176 words
        int h = i / 68, w = i % 68;
        if (w < 64) {
            float v0 = w1e[(size_t)(2 * w) * H_DIM + h0 + h];
            float v1 = w1e[(size_t)(2 * w + 1) * H_DIM + h0 + h];
            unsigned hi, lo;
            bsplit2(v0, v1, hi, lo);
            *(unsigned*)(dst + i * 4) = hi;
            *(unsigned*)(dst + W1HALF + i * 4) = lo;
        }
    }
    for (int i = threadIdx.x; i < W2HALF / 4; i += THREADS) {  // 2560 words
        int d = i / 20, w = i % 20;
        if (w < 16) {
            float v0 = w2e[(size_t)(h0 + 2 * w) * D_DIM + d];
            float v1 = w2e[(size_t)(h0 + 2 * w + 1) * D_DIM + d];
            unsigned hi, lo;
            bsplit2(v0, v1, hi, lo);
            *(unsigned*)(dst + W1CH + i * 4) = hi;
            *(unsigned*)(dst + W1CH + W2HALF + i * 4) = lo;
        }
    }
}

// ---------------- kernel 1: router (known-good) ----------------
__global__ __launch_bounds__(THREADS) void router_kernel(
    const float* __restrict__ x, const float* __restrict__ wg,
    const float* __restrict__ bg) {
    __shared__ float wgs[D_DIM * E_EXP];
    __shared__ float bgs[E_EXP];
    int tid = threadIdx.x;
    for (int i = tid; i < D_DIM * E_EXP; i += THREADS) wgs[i] = wg[i];
    if (tid < E_EXP) bgs[tid] = bg[tid];
    __syncthreads();

    int b = blockIdx.x * THREADS + tid;
    float acc[E_EXP];
#pragma unroll
    for (int e = 0; e < E_EXP; e++) acc[e] = bgs[e];
    const float4* xr = reinterpret_cast<const float4*>(x) + (size_t)b * (D_DIM / 4);
#pragma unroll 4
    for (int dq = 0; dq < D_DIM / 4; dq++) {
        float4 xv = xr[dq];
#pragma unroll
        for (int e = 0; e < E_EXP; e++) {
            acc[e] += xv.x * wgs[(dq * 4 + 0) * E_EXP + e];
            acc[e] += xv.y * wgs[(dq * 4 + 1) * E_EXP + e];
            acc[e] += xv.z * wgs[(dq * 4 + 2) * E_EXP + e];
            acc[e] += xv.w * wgs[(dq * 4 + 3) * E_EXP + e];
        }
    }
    int best = 0; float bv = acc[0];
#pragma unroll
    for (int e = 1; e < E_EXP; e++)
        if (acc[e] > bv) { bv = acc[e]; best = e; }

    unsigned lane = tid & 31;
    unsigned mask = __match_any_sync(0xffffffffu, best);
    int leader = __ffs(mask) - 1;
    int rank = __popc(mask & ((1u << lane) - 1u));
    int base = 0;
    if ((int)lane == leader) base = atomicAdd(&g_cnt[best], __popc(mask));
    base = __shfl_sync(0xffffffffu, base, leader);
    g_tok[best * B_TOK + base + rank] = b;
}

// ---------------- kernel 2: grouped MLP on HMMA, 2 CTAs/SM ----------------
__global__ __launch_bounds__(THREADS, 2) void moe_mma_kernel(
    const float* __restrict__ x, float* __restrict__ out) {
    extern __shared__ char smem[];
    int e = blockIdx.x;
    int cnt = g_cnt[e];
    int start = blockIdx.y * TM;
    if (start >= cnt) return;
    int ntok = min(TM, cnt - start);
    int tid = threadIdx.x, wid = tid >> 5, lane = tid & 31;
    int g = lane >> 2, tg = lane & 3;
    int m0 = (wid & 3) * 16;
    int n0a = (wid >> 2) * 16;  // GEMM1 n-offset (32 cols over 2 warp groups)
    int n0b = (wid >> 2) * 64;  // GEMM2 n-offset (128 cols over 2 warp groups)
    unsigned sb = smem_u32(smem);

    int* toks = (int*)(smem + OFF_TOKS);
    if (tid < TM) toks[tid] = (tid < ntok) ? g_tok[e * B_TOK + start + tid] : -1;
    __syncthreads();

    // ---- gather X tile [64][128] fp32 -> split bf16 hi/lo (row stride 272B)
    {
        int m = tid >> 2, q4 = tid & 3;
        int t = toks[m];
        const float4* xr = reinterpret_cast<const float4*>(x) +
                           (size_t)(t < 0 ? 0 : t) * 32 + q4 * 8;
#pragma unroll
        for (int i = 0; i < 8; i++) {
            float4 v = (t >= 0) ? xr[i] : make_float4(0.f, 0.f, 0.f, 0.f);
            int d = q4 * 32 + i * 4;
            unsigned hi, lo;
            bsplit2(v.x, v.y, hi, lo);
            *(unsigned*)(smem + OFF_XH + m * 272 + d * 2) = hi;
            *(unsigned*)(smem + OFF_XL + m * 272 + d * 2) = lo;
            bsplit2(v.z, v.w, hi, lo);
            *(unsigned*)(smem + OFF_XH + m * 272 + d * 2 + 4) = hi;
            *(unsigned*)(smem + OFF_XL + m * 272 + d * 2 + 4) = lo;
        }
    }

    // ---- prologue: prefetch W1(0) into w1 buffer 0
    {
        const unsigned char* src = g_wt[e][0];
        unsigned dst = sb + OFF_W1;
        for (int i = tid; i < W1CH / 16; i += THREADS)
            cp_async16(dst + i * 16, src + i * 16);
        CP_COMMIT();
    }

    float oacc[8][4];
#pragma unroll
    for (int i = 0; i < 8; i++)
#pragma unroll
        for (int j = 0; j < 4; j++) oacc[i][j] = 0.f;

    for (int c = 0; c < NCHUNK; c++) {
        __syncthreads();  // prev GEMM2 readers of W2/A2 done; X stores done (c==0)

        // issue W2(c) copy (overlaps GEMM1), then W1(c+1) prefetch
        {
            const unsigned char* s2 = g_wt[e][c] + W1CH;
            unsigned d2 = sb + OFF_W2;
            for (int i = tid; i < W2CH / 16; i += THREADS)
                cp_async16(d2 + i * 16, s2 + i * 16);
            CP_COMMIT();
            int cn = (c + 1) & (NCHUNK - 1);   // last iter: harmless dummy refetch
            const unsigned char* s1 = g_wt[e][cn];
            unsigned d1 = sb + OFF_W1 + ((c + 1) & 1) * W1CH;
            for (int i = tid; i < W1CH / 16; i += THREADS)
                cp_async16(d1 + i * 16, s1 + i * 16);
            CP_COMMIT();
        }
        CP_WAIT(2);       // W1(c) complete (this thread)
        __syncthreads();  // W1(c) visible to all

        const char* W1H = smem + OFF_W1 + (c & 1) * W1CH;
        const char* W1L = W1H + W1HALF;

        // ---- GEMM1: C1[16x16 per warp] = X @ W1c^T, 3-MMA split, K=128
        float acc1[2][4];
#pragma unroll
        for (int i = 0; i < 2; i++)
#pragma unroll
            for (int j = 0; j < 4; j++) acc1[i][j] = 0.f;

#pragma unroll
        for (int s = 0; s < 8; s++) {
            int kb = s * 16;
            unsigned ah[4], al[4];
            unsigned rb = (unsigned)(m0 + g) * 272 + kb * 2 + tg * 4;
            ah[0] = *(const unsigned*)(smem + OFF_XH + rb);
            ah[1] = *(const unsigned*)(smem + OFF_XH + rb + 8 * 272);
            ah[2] = *(const unsigned*)(smem + OFF_XH + rb + 16);
            ah[3] = *(const unsigned*)(smem + OFF_XH + rb + 8 * 272 + 16);
            al[0] = *(const unsigned*)(smem + OFF_XL + rb);
            al[1] = *(const unsigned*)(smem + OFF_XL + rb + 8 * 272);
            al[2] = *(const unsigned*)(smem + OFF_XL + rb + 16);
            al[3] = *(const unsigned*)(smem + OFF_XL + rb + 8 * 272 + 16);
#pragma unroll
            for (int nf = 0; nf < 2; nf++) {
                int h = n0a + nf * 8 + g;
                unsigned bb = (unsigned)h * 272 + ((unsigned)(kb >> 1) + tg) * 4;
                unsigned bh[2], bl[2];
                bh[0] = *(const unsigned*)(W1H + bb);
                bh[1] = *(const unsigned*)(W1H + bb + 16);
                bl[0] = *(const unsigned*)(W1L + bb);
                bl[1] = *(const unsigned*)(W1L + bb + 16);
                mma16816(acc1[nf], ah, bh);
                mma16816(acc1[nf], ah, bl);
                mma16816(acc1[nf], al, bh);
            }
        }

        // ---- GELU + split -> A2[m][h] hi/lo (row stride 80B)
#pragma unroll
        for (int nf = 0; nf < 2; nf++) {
            int col = n0a + nf * 8 + tg * 2;
            unsigned hi, lo;
            bsplit2(gelu(acc1[nf][0]), gelu(acc1[nf][1]), hi, lo);
            *(unsigned*)(smem + OFF_A2H + (m0 + g) * 80 + col * 2) = hi;
            *(unsigned*)(smem + OFF_A2L + (m0 + g) * 80 + col * 2) = lo;
            bsplit2(gelu(acc1[nf][2]), gelu(acc1[nf][3]), hi, lo);
            *(unsigned*)(smem + OFF_A2H + (m0 + g + 8) * 80 + col * 2) = hi;
            *(unsigned*)(smem + OFF_A2L + (m0 + g + 8) * 80 + col * 2) = lo;
        }
        CP_WAIT(1);       // W2(c) complete (W1(c+1) still pending)
        __syncthreads();  // A2 + W2 visible

        const char* W2H = smem + OFF_W2;
        const char* W2L = W2H + W2HALF;

        // ---- GEMM2: out[16x64 per warp] += gelu(H) @ W2c^T, K=32
#pragma unroll
        for (int s = 0; s < 2; s++) {
            int kb = s * 16;
            unsigned ah[4], al[4];
            unsigned rb = (unsigned)(m0 + g) * 80 + kb * 2 + tg * 4;
            ah[0] = *(const unsigned*)(smem + OFF_A2H + rb);
            ah[1] = *(const unsigned*)(smem + OFF_A2H + rb + 8 * 80);
            ah[2] = *(const unsigned*)(smem + OFF_A2H + rb + 16);
            ah[3] = *(const unsigned*)(smem + OFF_A2H + rb + 8 * 80 + 16);
            al[0] = *(const unsigned*)(smem + OFF_A2L + rb);
            al[1] = *(const unsigned*)(smem + OFF_A2L + rb + 8 * 80);
            al[2] = *(const unsigned*)(smem + OFF_A2L + rb + 16);
            al[3] = *(const unsigned*)(smem + OFF_A2L + rb + 8 * 80 + 16);
#pragma unroll
            for (int nf = 0; nf < 8; nf++) {
                int d = n0b + nf * 8 + g;
                unsigned bb = (unsigned)d * 80 + ((unsigned)(kb >> 1) + tg) * 4;
                unsigned bh[2], bl[2];
                bh[0] = *(const unsigned*)(W2H + bb);
                bh[1] = *(const unsigned*)(W2H + bb + 16);
                bl[0] = *(const unsigned*)(W2L + bb);
                bl[1] = *(const unsigned*)(W2L + bb + 16);
                mma16816(oacc[nf], ah, bh);
                mma16816(oacc[nf], ah, bl);
                mma16816(oacc[nf], al, bh);
            }
        }
    }

    // ---- scatter output rows
#pragma unroll
    for (int nf = 0; nf < 8; nf++) {
        int col = n0b + nf * 8 + tg * 2;
        int m1 = m0 + g, m2 = m0 + g + 8;
        if (m1 < ntok) {
            int t = toks[m1];
            *reinterpret_cast<float2*>(out + (size_t)t * D_DIM + col) =
                make_float2(oacc[nf][0], oacc[nf][1]);
        }
        if (m2 < ntok) {
            int t = toks[m2];
            *reinterpret_cast<float2*>(out + (size_t)t * D_DIM + col) =
                make_float2(oacc[nf][2], oacc[nf][3]);
        }
    }
}

// ---------------- launcher ----------------
extern "C" void kernel_launch(void* const* d_in, const int* in_sizes, int n_in,
                              void* d_out, int out_size) {
    const float* x  = (const float*)d_in[0];
    const float* w1 = (const float*)d_in[1];
    const float* w2 = (const float*)d_in[2];
    const float* wg = (const float*)d_in[3];
    const float* bg = (const float*)d_in[4];
    float* out = (float*)d_out;

    cudaFuncSetAttribute(moe_mma_kernel, cudaFuncAttributeMaxDynamicSharedMemorySize,
                         SMEM_TOTAL);

    zero_cnt_kernel<<<1, E_EXP>>>();
    router_kernel<<<B_TOK / THREADS, THREADS>>>(x, wg, bg);
    dim3 pgrid(E_EXP, NCHUNK);
    prep_kernel<<<pgrid, THREADS>>>(w1, w2);
    dim3 grid(E_EXP, B_TOK / TM);  // capacity grid: no token dropped
    moe_mma_kernel<<<grid, THREADS, SMEM_TOTAL>>>(x, out);
}

// round 12
// speedup vs baseline: 3.9463x; 1.0789x over previous
#include <cuda_runtime.h>
#include <cuda_bf16.h>
#include <math.h>

#define B_TOK 32768
#define D_DIM 128
#define H_DIM 512
#define E_EXP 16
#define TM 64
#define NH 32
#define NCHUNK (H_DIM / NH)   // 16
#define THREADS 256

// weight image sizes (bytes)
#define W1HALF 8704           // 32 h-rows x 272B (64 d-pair words + 4 pad words)
#define W1CH   (2 * W1HALF)   // 17408 (hi + lo)
#define W2HALF 10240          // 128 d-rows x 80B (16 j-pair words + 4 pad words)
#define W2CH   (2 * W2HALF)   // 20480
#define CHUNK_BYTES (W1CH + W2CH)  // 37888

// SMEM layout (bytes)
#define OFF_TOKS 0
#define OFF_XH   256
#define OFF_XL   (OFF_XH + 17408)
#define OFF_A2H  (OFF_XL + 17408)
#define OFF_A2L  (OFF_A2H + 5120)
#define OFF_W1   (OFF_A2L + 5120)            // double buffer: + buf*W1CH, each [H|L]
#define OFF_W2   (OFF_W1 + 2 * W1CH)         // single buffer: [H|L]
#define SMEM_TOTAL (OFF_W2 + W2CH)           // 100608 -> 2 CTAs/SM

// ---------------- device scratch ----------------
__device__ int g_cnt[E_EXP];
__device__ int g_tok[E_EXP * B_TOK];
__device__ unsigned char g_wt[E_EXP][NCHUNK][CHUNK_BYTES];  // pre-split weight images

// ---------------- helpers ----------------
__device__ __forceinline__ void bsplit2(float v0, float v1, unsigned& hi, unsigned& lo) {
    __nv_bfloat162 h = __floats2bfloat162_rn(v0, v1);
    float r0 = v0 - __bfloat162float(h.x);
    float r1 = v1 - __bfloat162float(h.y);
    __nv_bfloat162 l = __floats2bfloat162_rn(r0, r1);
    hi = *(unsigned*)&h;
    lo = *(unsigned*)&l;
}
__device__ __forceinline__ float gelu(float h) {
    return 0.5f * h * (1.0f + erff(h * 0.70710678118654752440f));
}
__device__ __forceinline__ unsigned smem_u32(const void* p) {
    unsigned a;
    asm("{ .reg .u64 t; cvta.to.shared.u64 t, %1; cvt.u32.u64 %0, t; }"
        : "=r"(a) : "l"(p));
    return a;
}
__device__ __forceinline__ void cp_async16(unsigned dst, const void* src) {
    asm volatile("cp.async.cg.shared.global [%0], [%1], 16;"
                 :: "r"(dst), "l"(src) : "memory");
}
#define CP_COMMIT() asm volatile("cp.async.commit_group;" ::: "memory")
#define CP_WAIT(n)  asm volatile("cp.async.wait_group %0;" :: "n"(n) : "memory")

// ldmatrix x4: four 8x8 b16 tiles, one per 8-thread address group
__device__ __forceinline__ void ldsm4(unsigned addr, unsigned* r) {
    asm volatile("ldmatrix.sync.aligned.m8n8.x4.shared.b16 {%0,%1,%2,%3}, [%4];"
                 : "=r"(r[0]), "=r"(r[1]), "=r"(r[2]), "=r"(r[3]) : "r"(addr));
}

// D += A * B  (m16n8k16, bf16 in, fp32 acc) — base-PTX HMMA, valid on sm_103
__device__ __forceinline__ void mma16816(float* c, const unsigned* a, const unsigned* b) {
    asm volatile(
        "mma.sync.aligned.m16n8k16.row.col.f32.bf16.bf16.f32 "
        "{%0,%1,%2,%3}, {%4,%5,%6,%7}, {%8,%9}, {%0,%1,%2,%3};"
        : "+f"(c[0]), "+f"(c[1]), "+f"(c[2]), "+f"(c[3])
        : "r"(a[0]), "r"(a[1]), "r"(a[2]), "r"(a[3]), "r"(b[0]), "r"(b[1]));
}

// ---------------- kernel P: pre-split weights + zero counters ----------------
__global__ __launch_bounds__(THREADS) void prep_kernel(
    const float* __restrict__ w1, const float* __restrict__ w2) {
    if (blockIdx.x == 0 && blockIdx.y == 0 && threadIdx.x < E_EXP)
        g_cnt[threadIdx.x] = 0;
    int e = blockIdx.x, c = blockIdx.y;
    int h0 = c * NH;
    const float* w1e = w1 + (size_t)e * D_DIM * H_DIM;
    const float* w2e = w2 + (size_t)e * H_DIM * D_DIM;
    unsigned char* dst = g_wt[e][c];

    for (int i = threadIdx.x; i < W1HALF / 4; i += THREADS) {  // 2176 words
        int h = i / 68, w = i % 68;
        if (w < 64) {
            float v0 = w1e[(size_t)(2 * w) * H_DIM + h0 + h];
            float v1 = w1e[(size_t)(2 * w + 1) * H_DIM + h0 + h];
            unsigned hi, lo;
            bsplit2(v0, v1, hi, lo);
            *(unsigned*)(dst + i * 4) = hi;
            *(unsigned*)(dst + W1HALF + i * 4) = lo;
        }
    }
    for (int i = threadIdx.x; i < W2HALF / 4; i += THREADS) {  // 2560 words
        int d = i / 20, w = i % 20;
        if (w < 16) {
            float v0 = w2e[(size_t)(h0 + 2 * w) * D_DIM + d];
            float v1 = w2e[(size_t)(h0 + 2 * w + 1) * D_DIM + d];
            unsigned hi, lo;
            bsplit2(v0, v1, hi, lo);
            *(unsigned*)(dst + W1CH + i * 4) = hi;
            *(unsigned*)(dst + W1CH + W2HALF + i * 4) = lo;
        }
    }
}

// ---------------- kernel 1: router (known-good) ----------------
__global__ __launch_bounds__(THREADS) void router_kernel(
    const float* __restrict__ x, const float* __restrict__ wg,
    const float* __restrict__ bg) {
    __shared__ float wgs[D_DIM * E_EXP];
    __shared__ float bgs[E_EXP];
    int tid = threadIdx.x;
    for (int i = tid; i < D_DIM * E_EXP; i += THREADS) wgs[i] = wg[i];
    if (tid < E_EXP) bgs[tid] = bg[tid];
    __syncthreads();

    int b = blockIdx.x * THREADS + tid;
    float acc[E_EXP];
#pragma unroll
    for (int e = 0; e < E_EXP; e++) acc[e] = bgs[e];
    const float4* xr = reinterpret_cast<const float4*>(x) + (size_t)b * (D_DIM / 4);
#pragma unroll 4
    for (int dq = 0; dq < D_DIM / 4; dq++) {
        float4 xv = xr[dq];
#pragma unroll
        for (int e = 0; e < E_EXP; e++) {
            acc[e] += xv.x * wgs[(dq * 4 + 0) * E_EXP + e];
            acc[e] += xv.y * wgs[(dq * 4 + 1) * E_EXP + e];
            acc[e] += xv.z * wgs[(dq * 4 + 2) * E_EXP + e];
            acc[e] += xv.w * wgs[(dq * 4 + 3) * E_EXP + e];
        }
    }
    int best = 0; float bv = acc[0];
#pragma unroll
    for (int e = 1; e < E_EXP; e++)
        if (acc[e] > bv) { bv = acc[e]; best = e; }

    unsigned lane = tid & 31;
    unsigned mask = __match_any_sync(0xffffffffu, best);
    int leader = __ffs(mask) - 1;
    int rank = __popc(mask & ((1u << lane) - 1u));
    int base = 0;
    if ((int)lane == leader) base = atomicAdd(&g_cnt[best], __popc(mask));
    base = __shfl_sync(0xffffffffu, base, leader);
    g_tok[best * B_TOK + base + rank] = b;
}

// ---------------- kernel 2: grouped MLP on HMMA + LDSM, 2 CTAs/SM ----------------
__global__ __launch_bounds__(THREADS, 2) void moe_mma_kernel(
    const float* __restrict__ x, float* __restrict__ out) {
    extern __shared__ char smem[];
    int e = blockIdx.x;
    int cnt = g_cnt[e];
    int start = blockIdx.y * TM;
    if (start >= cnt) return;
    int ntok = min(TM, cnt - start);
    int tid = threadIdx.x, wid = tid >> 5, lane = tid & 31;
    int g = lane >> 2, tg = lane & 3;
    int m0 = (wid & 3) * 16;
    int n0a = (wid >> 2) * 16;  // GEMM1 n-offset (32 cols over 2 warp groups)
    int n0b = (wid >> 2) * 64;  // GEMM2 n-offset (128 cols over 2 warp groups)
    unsigned sb = smem_u32(smem);

    int* toks = (int*)(smem + OFF_TOKS);
    if (tid < TM) toks[tid] = (tid < ntok) ? g_tok[e * B_TOK + start + tid] : -1;
    __syncthreads();

    // ---- gather X tile [64][128] fp32 -> split bf16 hi/lo (row stride 272B)
    {
        int m = tid >> 2, q4 = tid & 3;
        int t = toks[m];
        const float4* xr = reinterpret_cast<const float4*>(x) +
                           (size_t)(t < 0 ? 0 : t) * 32 + q4 * 8;
#pragma unroll
        for (int i = 0; i < 8; i++) {
            float4 v = (t >= 0) ? xr[i] : make_float4(0.f, 0.f, 0.f, 0.f);
            int d = q4 * 32 + i * 4;
            unsigned hi, lo;
            bsplit2(v.x, v.y, hi, lo);
            *(unsigned*)(smem + OFF_XH + m * 272 + d * 2) = hi;
            *(unsigned*)(smem + OFF_XL + m * 272 + d * 2) = lo;
            bsplit2(v.z, v.w, hi, lo);
            *(unsigned*)(smem + OFF_XH + m * 272 + d * 2 + 4) = hi;
            *(unsigned*)(smem + OFF_XL + m * 272 + d * 2 + 4) = lo;
        }
    }

    // ---- prologue: prefetch W1(0) into w1 buffer 0
    {
        const unsigned char* src = g_wt[e][0];
        unsigned dst = sb + OFF_W1;
        for (int i = tid; i < W1CH / 16; i += THREADS)
            cp_async16(dst + i * 16, src + i * 16);
        CP_COMMIT();
    }

    // ---- per-thread LDSM base addresses (hoisted out of all loops)
    // A-tiles order (r0k0),(r8k0),(r0k8),(r8k8): row+=(lane>>3&1)*8, koff=(lane>>4&1)*16
    // B-tiles order (n0k0),(n0k8),(n8k0),(n8k8): row+=(lane>>4&1)*8, koff=(lane>>3&1)*16
    unsigned xa = sb + OFF_XH +
                  (unsigned)(m0 + ((lane >> 3) & 1) * 8 + (lane & 7)) * 272 +
                  ((lane >> 4) & 1) * 16;
    unsigned xla = xa + (OFF_XL - OFF_XH);
    unsigned b1off = (unsigned)(n0a + ((lane >> 4) & 1) * 8 + (lane & 7)) * 272 +
                     ((lane >> 3) & 1) * 16;
    unsigned a2a = sb + OFF_A2H +
                   (unsigned)(m0 + ((lane >> 3) & 1) * 8 + (lane & 7)) * 80 +
                   ((lane >> 4) & 1) * 16;
    unsigned a2la = a2a + (OFF_A2L - OFF_A2H);
    unsigned b2a = sb + OFF_W2 +
                   (unsigned)(n0b + ((lane >> 4) & 1) * 8 + (lane & 7)) * 80 +
                   ((lane >> 3) & 1) * 16;

    float oacc[8][4];
#pragma unroll
    for (int i = 0; i < 8; i++)
#pragma unroll
        for (int j = 0; j < 4; j++) oacc[i][j] = 0.f;

    for (int c = 0; c < NCHUNK; c++) {
        __syncthreads();  // prev GEMM2 readers of W2/A2 done; X stores done (c==0)

        // issue W2(c) copy (overlaps GEMM1), then W1(c+1) prefetch
        {
            const unsigned char* s2 = g_wt[e][c] + W1CH;
            unsigned d2 = sb + OFF_W2;
            for (int i = tid; i < W2CH / 16; i += THREADS)
                cp_async16(d2 + i * 16, s2 + i * 16);
            CP_COMMIT();
            int cn = (c + 1) & (NCHUNK - 1);   // last iter: harmless dummy refetch
            const unsigned char* s1 = g_wt[e][cn];
            unsigned d1 = sb + OFF_W1 + ((c + 1) & 1) * W1CH;
            for (int i = tid; i < W1CH / 16; i += THREADS)
                cp_async16(d1 + i * 16, s1 + i * 16);
            CP_COMMIT();
        }
        CP_WAIT(2);       // W1(c) complete (this thread)
        __syncthreads();  // W1(c) visible to all

        unsigned w1b = sb + OFF_W1 + (c & 1) * W1CH + b1off;

        // ---- GEMM1: C1[16x16 per warp] = X @ W1c^T, 3-MMA split, K=128
        float acc1[2][4];
#pragma unroll
        for (int i = 0; i < 2; i++)
#pragma unroll
            for (int j = 0; j < 4; j++) acc1[i][j] = 0.f;

#pragma unroll
        for (int s = 0; s < 8; s++) {
            unsigned ah[4], al[4], bh[4], bl[4];
            ldsm4(xa + s * 32, ah);
            ldsm4(xla + s * 32, al);
            ldsm4(w1b + s * 32, bh);
            ldsm4(w1b + W1HALF + s * 32, bl);
            mma16816(acc1[0], ah, bh);
            mma16816(acc1[0], ah, bl);
            mma16816(acc1[0], al, bh);
            mma16816(acc1[1], ah, bh + 2);
            mma16816(acc1[1], ah, bl + 2);
            mma16816(acc1[1], al, bh + 2);
        }

        // ---- GELU + split -> A2[m][h] hi/lo (row stride 80B)
#pragma unroll
        for (int nf = 0; nf < 2; nf++) {
            int col = n0a + nf * 8 + tg * 2;
            unsigned hi, lo;
            bsplit2(gelu(acc1[nf][0]), gelu(acc1[nf][1]), hi, lo);
            *(unsigned*)(smem + OFF_A2H + (m0 + g) * 80 + col * 2) = hi;
            *(unsigned*)(smem + OFF_A2L + (m0 + g) * 80 + col * 2) = lo;
            bsplit2(gelu(acc1[nf][2]), gelu(acc1[nf][3]), hi, lo);
            *(unsigned*)(smem + OFF_A2H + (m0 + g + 8) * 80 + col * 2) = hi;
            *(unsigned*)(smem + OFF_A2L + (m0 + g + 8) * 80 + col * 2) = lo;
        }
        CP_WAIT(1);       // W2(c) complete (W1(c+1) still pending)
        __syncthreads();  // A2 + W2 visible

        // ---- GEMM2: out[16x64 per warp] += gelu(H) @ W2c^T, K=32
#pragma unroll
        for (int s = 0; s < 2; s++) {
            unsigned ah[4], al[4];
            ldsm4(a2a + s * 32, ah);
            ldsm4(a2la + s * 32, al);
#pragma unroll
            for (int q = 0; q < 4; q++) {
                unsigned bh[4], bl[4];
                ldsm4(b2a + q * 1280 + s * 32, bh);
                ldsm4(b2a + W2HALF + q * 1280 + s * 32, bl);
                mma16816(oacc[2 * q], ah, bh);
                mma16816(oacc[2 * q], ah, bl);
                mma16816(oacc[2 * q], al, bh);
                mma16816(oacc[2 * q + 1], ah, bh + 2);
                mma16816(oacc[2 * q + 1], ah, bl + 2);
                mma16816(oacc[2 * q + 1], al, bh + 2);
            }
        }
    }

    // ---- scatter output rows
#pragma unroll
    for (int nf = 0; nf < 8; nf++) {
        int col = n0b + nf * 8 + tg * 2;
        int m1 = m0 + g, m2 = m0 + g + 8;
        if (m1 < ntok) {
            int t = toks[m1];
            *reinterpret_cast<float2*>(out + (size_t)t * D_DIM + col) =
                make_float2(oacc[nf][0], oacc[nf][1]);
        }
        if (m2 < ntok) {
            int t = toks[m2];
            *reinterpret_cast<float2*>(out + (size_t)t * D_DIM + col) =
                make_float2(oacc[nf][2], oacc[nf][3]);
        }
    }
}

// ---------------- launcher ----------------
extern "C" void kernel_launch(void* const* d_in, const int* in_sizes, int n_in,
                              void* d_out, int out_size) {
    const float* x  = (const float*)d_in[0];
    const float* w1 = (const float*)d_in[1];
    const float* w2 = (const float*)d_in[2];
    const float* wg = (const float*)d_in[3];
    const float* bg = (const float*)d_in[4];
    float* out = (float*)d_out;

    cudaFuncSetAttribute(moe_mma_kernel, cudaFuncAttributeMaxDynamicSharedMemorySize,
                         SMEM_TOTAL);

    dim3 pgrid(E_EXP, NCHUNK);
    prep_kernel<<<pgrid, THREADS>>>(w1, w2);   // also zeroes g_cnt (block 0,0)
    router_kernel<<<B_TOK / THREADS, THREADS>>>(x, wg, bg);
    dim3 grid(E_EXP, B_TOK / TM);  // capacity grid: no token dropped
    moe_mma_kernel<<<grid, THREADS, SMEM_TOTAL>>>(x, out);
}